// round 14
// baseline (speedup 1.0000x reference)
#include <cuda_runtime.h>
#include <cuda_bf16.h>
#include <cstdint>
#include <cstddef>

#define BATCH 32
#define TQ    512
#define TK    2048
#define DIM   512

// ---------------------------------------------------------------------------
// Static device scratch.
// ---------------------------------------------------------------------------
__device__ float    g_S [(size_t)BATCH * TQ * TK];
__device__ uint16_t g_Q2[(size_t)BATCH * TQ  * (2 * DIM)];
__device__ uint16_t g_E2[(size_t)BATCH * TK  * (2 * DIM)];
__device__ uint16_t g_Et[(size_t)BATCH * DIM * (2 * TK)];
__device__ uint16_t g_P2[(size_t)BATCH * TQ  * (2 * TK)];

// ---------------------------------------------------------------------------
// Base-PTX helpers (sm_80+ only — must compile for compute_103)
// ---------------------------------------------------------------------------
__device__ __forceinline__ uint32_t smem_u32(const void* p) {
    uint32_t a;
    asm("{ .reg .u64 t; cvta.to.shared.u64 t, %1; cvt.u32.u64 %0, t; }"
        : "=r"(a) : "l"(p));
    return a;
}

__device__ __forceinline__ void cp16(uint32_t saddr, const void* gaddr) {
    asm volatile("cp.async.cg.shared.global [%0], [%1], 16;\n"
                 :: "r"(saddr), "l"(gaddr));
}
__device__ __forceinline__ void cp_commit() {
    asm volatile("cp.async.commit_group;\n" ::: "memory");
}
template <int N>
__device__ __forceinline__ void cp_wait() {
    asm volatile("cp.async.wait_group %0;\n" :: "n"(N) : "memory");
}

__device__ __forceinline__ void ldsm4(uint32_t& r0, uint32_t& r1,
                                      uint32_t& r2, uint32_t& r3, uint32_t a) {
    asm volatile("ldmatrix.sync.aligned.m8n8.x4.shared.b16 {%0,%1,%2,%3}, [%4];\n"
                 : "=r"(r0), "=r"(r1), "=r"(r2), "=r"(r3) : "r"(a));
}

__device__ __forceinline__ void mma16816(float* c, const uint32_t* a,
                                         const uint32_t* b) {
    asm volatile(
        "mma.sync.aligned.m16n8k16.row.col.f32.bf16.bf16.f32 "
        "{%0,%1,%2,%3}, {%4,%5,%6,%7}, {%8,%9}, {%0,%1,%2,%3};\n"
        : "+f"(c[0]), "+f"(c[1]), "+f"(c[2]), "+f"(c[3])
        : "r"(a[0]), "r"(a[1]), "r"(a[2]), "r"(a[3]), "r"(b[0]), "r"(b[1]));
}

// ---------------------------------------------------------------------------
// fp32 -> (bf16 hi, bf16 lo) split helpers
// ---------------------------------------------------------------------------
__device__ __forceinline__ void split4(float4 v, uint2& hi, uint2& lo) {
    __nv_bfloat16 h0 = __float2bfloat16_rn(v.x);
    __nv_bfloat16 h1 = __float2bfloat16_rn(v.y);
    __nv_bfloat16 h2 = __float2bfloat16_rn(v.z);
    __nv_bfloat16 h3 = __float2bfloat16_rn(v.w);
    __nv_bfloat16 l0 = __float2bfloat16_rn(v.x - __bfloat162float(h0));
    __nv_bfloat16 l1 = __float2bfloat16_rn(v.y - __bfloat162float(h1));
    __nv_bfloat16 l2 = __float2bfloat16_rn(v.z - __bfloat162float(h2));
    __nv_bfloat16 l3 = __float2bfloat16_rn(v.w - __bfloat162float(h3));
    hi.x = (uint32_t)__bfloat16_as_ushort(h0) | ((uint32_t)__bfloat16_as_ushort(h1) << 16);
    hi.y = (uint32_t)__bfloat16_as_ushort(h2) | ((uint32_t)__bfloat16_as_ushort(h3) << 16);
    lo.x = (uint32_t)__bfloat16_as_ushort(l0) | ((uint32_t)__bfloat16_as_ushort(l1) << 16);
    lo.y = (uint32_t)__bfloat16_as_ushort(l2) | ((uint32_t)__bfloat16_as_ushort(l3) << 16);
}

// ---------------------------------------------------------------------------
// splitQ: Q[r, 0..511] fp32 -> g_Q2[r, hi(512)|lo(512)] bf16
// ---------------------------------------------------------------------------
__global__ __launch_bounds__(256) void splitQ_kernel(const float* __restrict__ Q) {
    size_t t = (size_t)blockIdx.x * 256 + threadIdx.x;
    if (t >= (size_t)BATCH * TQ * 64) return;
    size_t row = t >> 6;
    int g = (int)(t & 63);
    const float4* p = (const float4*)(Q + row * DIM) + g * 2;
    float4 a = p[0], b = p[1];
    uint2 h0, l0, h1, l1;
    split4(a, h0, l0); split4(b, h1, l1);
    uint16_t* orow = g_Q2 + row * (2 * DIM);
    *(uint4*)(orow + g * 8)       = make_uint4(h0.x, h0.y, h1.x, h1.y);
    *(uint4*)(orow + DIM + g * 8) = make_uint4(l0.x, l0.y, l1.x, l1.y);
}

// ---------------------------------------------------------------------------
// Fused splitE + transposeE: read each 64x64 E tile ONCE, emit both
//   g_E2[b, k, hi(d)|lo(d)]  (row-major split)
//   g_Et[b, d, hi(k)|lo(k)]  (transposed split)
// ---------------------------------------------------------------------------
__global__ __launch_bounds__(256)
void splitE_transpose_kernel(const float* __restrict__ Eg) {
    __shared__ float t[64][65];
    const int b = blockIdx.z, k0 = blockIdx.x * 64, d0 = blockIdx.y * 64;
    const float* E = Eg + (size_t)b * TK * DIM;
    const int tid = threadIdx.x;
#pragma unroll
    for (int i = 0; i < 4; ++i) {
        int idx = tid + i * 256;
        int r = idx >> 4, c4 = idx & 15;
        float4 v = *(const float4*)(E + (size_t)(k0 + r) * DIM + d0 + c4 * 4);
        t[r][c4 * 4 + 0] = v.x; t[r][c4 * 4 + 1] = v.y;
        t[r][c4 * 4 + 2] = v.z; t[r][c4 * 4 + 3] = v.w;
    }
    __syncthreads();

    // row-major split output (g_E2)
    uint16_t* E2 = g_E2 + (size_t)b * TK * (2 * DIM);
#pragma unroll
    for (int i = 0; i < 2; ++i) {
        int task = tid + i * 256;          // 0..511
        int r = task >> 3, g = task & 7;   // row, 8-col group
        float4 a = make_float4(t[r][g*8+0], t[r][g*8+1], t[r][g*8+2], t[r][g*8+3]);
        float4 c = make_float4(t[r][g*8+4], t[r][g*8+5], t[r][g*8+6], t[r][g*8+7]);
        uint2 h0, l0, h1, l1;
        split4(a, h0, l0); split4(c, h1, l1);
        uint16_t* orow = E2 + (size_t)(k0 + r) * (2 * DIM);
        *(uint4*)(orow + d0 + g * 8)       = make_uint4(h0.x, h0.y, h1.x, h1.y);
        *(uint4*)(orow + DIM + d0 + g * 8) = make_uint4(l0.x, l0.y, l1.x, l1.y);
    }

    // transposed split output (g_Et)
    uint16_t* Et = g_Et + (size_t)b * DIM * (2 * TK);
#pragma unroll
    for (int i = 0; i < 2; ++i) {
        int task = tid + i * 256;
        int dr = task >> 3, g = task & 7;
        float4 a = make_float4(t[g*8+0][dr], t[g*8+1][dr], t[g*8+2][dr], t[g*8+3][dr]);
        float4 c = make_float4(t[g*8+4][dr], t[g*8+5][dr], t[g*8+6][dr], t[g*8+7][dr]);
        uint2 h0, l0, h1, l1;
        split4(a, h0, l0); split4(c, h1, l1);
        uint16_t* orow = Et + (size_t)(d0 + dr) * (2 * TK);
        *(uint4*)(orow + k0 + g * 8)      = make_uint4(h0.x, h0.y, h1.x, h1.y);
        *(uint4*)(orow + TK + k0 + g * 8) = make_uint4(l0.x, l0.y, l1.x, l1.y);
    }
}

// ---------------------------------------------------------------------------
// NT GEMM on mma.sync bf16 with FUSED 3-phase split per k-chunk.
// Each 32-k chunk stages BOTH hi and lo halves of A and B in smem
// (row = 128 B: segs 0-3 hi, segs 4-7 lo, XOR-swizzled seg^(row&7)).
// Per k16 step: mma hh (Ahi*Bhi), hl (Ahi*Blo), lh (Alo*Bhi) — fragments
// loaded once, used across phases. LDS:HMMA balanced 1:1.
// CTA tile 128x256, 512 threads (16 warps, warp tile 64x32), double buffer.
// MODE 0: S = Q2 * E2^T (Kp=512)    MODE 1: O = P2 * Et^T (Kp=2048)
// ---------------------------------------------------------------------------
#define ABUF 16384   // per A buffer: 128 rows * 128 B
#define BBUF 32768   // per B buffer: 256 rows * 128 B
#define BSOFF 32768  // B base = after 2 A buffers
#define GSM  98304

template <int MODE>
__global__ __launch_bounds__(512, 1)
void gemm_mma(float* __restrict__ Oout) {
    constexpr int Kp  = MODE ? 2048 : 512;
    constexpr int NCH = Kp / 32;          // chunks (16 / 64), each covers 3 phases
    constexpr int lda = MODE ? 2 * TK : 2 * DIM;
    constexpr int ldb = MODE ? 2 * TK : 2 * DIM;
    constexpr int ldc = MODE ? DIM : TK;

    extern __shared__ char smem[];
    const uint32_t asb = smem_u32(smem);
    const uint32_t bsb = asb + BSOFF;

    const int tid  = threadIdx.x;
    const int wid  = tid >> 5;
    const int lane = tid & 31;
    const int warp_m = wid & 1;           // 0..1  (64 rows each)
    const int warp_n = wid >> 1;          // 0..7  (32 cols each)

    const int b  = blockIdx.z;
    const int n0 = blockIdx.x * 256;
    const int q0 = blockIdx.y * 128;

    const uint16_t* A = (MODE ? g_P2 : g_Q2) + (size_t)b * TQ * lda + (size_t)q0 * lda;
    const uint16_t* B = (MODE ? g_Et : g_E2) +
                        (size_t)b * (size_t)(MODE ? DIM : TK) * ldb + (size_t)n0 * ldb;
    float* C = (MODE ? Oout + (size_t)b * TQ * DIM : g_S + (size_t)b * TQ * TK);

    // cp.async: A = 1024 16B-segs (2/thread), B = 2048 (4/thread).
    // segs 0-3 <- hi half (koff), segs 4-7 <- lo half (Kp + koff).
    auto issue_chunk = [&](int buf, int c) {
        const int koff = c * 32;
#pragma unroll
        for (int j = 0; j < 2; ++j) {
            int idx = tid + j * 512;
            int row = idx >> 3, seg = idx & 7;
            const uint16_t* src = A + (size_t)row * lda +
                (seg < 4 ? koff + seg * 8 : Kp + koff + (seg - 4) * 8);
            cp16(asb + buf * ABUF + row * 128 + ((seg ^ (row & 7)) << 4), src);
        }
#pragma unroll
        for (int j = 0; j < 4; ++j) {
            int idx = tid + j * 512;
            int row = idx >> 3, seg = idx & 7;
            const uint16_t* src = B + (size_t)row * ldb +
                (seg < 4 ? koff + seg * 8 : Kp + koff + (seg - 4) * 8);
            cp16(bsb + buf * BBUF + row * 128 + ((seg ^ (row & 7)) << 4), src);
        }
        cp_commit();
    };

    float acc[4][4][4];
#pragma unroll
    for (int i = 0; i < 4; ++i)
#pragma unroll
        for (int j = 0; j < 4; ++j)
#pragma unroll
            for (int k = 0; k < 4; ++k) acc[i][j][k] = 0.0f;

    // ldmatrix lane geometry (identical to validated R11 layout)
    const int aRowBase = warp_m * 64 + ((lane >> 3) & 1) * 8 + (lane & 7);
    const int aSegSel  = lane >> 4;                 // 0/1
    const int bRowBase = warp_n * 32 + ((lane >> 4) & 1) * 8 + (lane & 7);
    const int bSegSel  = (lane >> 3) & 1;           // 0/1

    int aRow[4], bRow[2];
#pragma unroll
    for (int mt = 0; mt < 4; ++mt) aRow[mt] = aRowBase + mt * 16;
#pragma unroll
    for (int np = 0; np < 2; ++np) bRow[np] = bRowBase + np * 16;

    issue_chunk(0, 0);

    for (int c = 0; c < NCH; ++c) {
        const int buf = c & 1;
        if (c + 1 < NCH) {
            issue_chunk(buf ^ 1, c + 1);
            cp_wait<1>();
        } else {
            cp_wait<0>();
        }
        __syncthreads();

        const uint32_t abase = asb + buf * ABUF;
        const uint32_t bbase = bsb + buf * BBUF;
#pragma unroll
        for (int ks = 0; ks < 2; ++ks) {
            // --- hi fragments ---
            uint32_t afh[4][4];
#pragma unroll
            for (int mt = 0; mt < 4; ++mt) {
                const int r = aRow[mt];
                const uint32_t ad =
                    abase + r * 128 + (((2 * ks + aSegSel) ^ (r & 7)) << 4);
                ldsm4(afh[mt][0], afh[mt][1], afh[mt][2], afh[mt][3], ad);
            }
            uint32_t bfh[4][2];
#pragma unroll
            for (int np = 0; np < 2; ++np) {
                const int r = bRow[np];
                const uint32_t bd =
                    bbase + r * 128 + (((2 * ks + bSegSel) ^ (r & 7)) << 4);
                ldsm4(bfh[np * 2][0], bfh[np * 2][1],
                      bfh[np * 2 + 1][0], bfh[np * 2 + 1][1], bd);
            }
            // hh
#pragma unroll
            for (int mt = 0; mt < 4; ++mt)
#pragma unroll
                for (int nt = 0; nt < 4; ++nt)
                    mma16816(acc[mt][nt], afh[mt], bfh[nt]);

            // --- B lo, then hl (Ahi still live) ---
            uint32_t bfl[4][2];
#pragma unroll
            for (int np = 0; np < 2; ++np) {
                const int r = bRow[np];
                const uint32_t bd =
                    bbase + r * 128 + (((4 + 2 * ks + bSegSel) ^ (r & 7)) << 4);
                ldsm4(bfl[np * 2][0], bfl[np * 2][1],
                      bfl[np * 2 + 1][0], bfl[np * 2 + 1][1], bd);
            }
#pragma unroll
            for (int mt = 0; mt < 4; ++mt)
#pragma unroll
                for (int nt = 0; nt < 4; ++nt)
                    mma16816(acc[mt][nt], afh[mt], bfl[nt]);

            // --- A lo, then lh (Bhi still live; Ahi dead) ---
            uint32_t afl[4][4];
#pragma unroll
            for (int mt = 0; mt < 4; ++mt) {
                const int r = aRow[mt];
                const uint32_t ad =
                    abase + r * 128 + (((4 + 2 * ks + aSegSel) ^ (r & 7)) << 4);
                ldsm4(afl[mt][0], afl[mt][1], afl[mt][2], afl[mt][3], ad);
            }
#pragma unroll
            for (int mt = 0; mt < 4; ++mt)
#pragma unroll
                for (int nt = 0; nt < 4; ++nt)
                    mma16816(acc[mt][nt], afl[mt], bfh[nt]);
        }
        __syncthreads();
    }

    // epilogue
    const int fr = lane >> 2;
    const int fc = (lane & 3) * 2;
#pragma unroll
    for (int mt = 0; mt < 4; ++mt) {
        const int row = q0 + warp_m * 64 + mt * 16 + fr;
#pragma unroll
        for (int nt = 0; nt < 4; ++nt) {
            const int col = n0 + warp_n * 32 + nt * 8 + fc;
            *(float2*)&C[(size_t)row * ldc + col] =
                make_float2(acc[mt][nt][0], acc[mt][nt][1]);
            *(float2*)&C[(size_t)(row + 8) * ldc + col] =
                make_float2(acc[mt][nt][2], acc[mt][nt][3]);
        }
    }
}

// ---------------------------------------------------------------------------
// Softmax over S rows; emits P split: g_P2[row] = [Phi(2048) | Plo(2048)]
// ---------------------------------------------------------------------------
__global__ __launch_bounds__(256)
void softmax_split_kernel() {
    const int row = blockIdx.x;
    const float4* S4 = (const float4*)g_S + (size_t)row * (TK / 4);
    uint16_t* P = g_P2 + (size_t)row * (2 * TK);
    const int tid = threadIdx.x;

    float4 v0 = S4[tid];
    float4 v1 = S4[tid + 256];

    float m = fmaxf(fmaxf(fmaxf(v0.x, v0.y), fmaxf(v0.z, v0.w)),
                    fmaxf(fmaxf(v1.x, v1.y), fmaxf(v1.z, v1.w)));
#pragma unroll
    for (int o = 16; o > 0; o >>= 1)
        m = fmaxf(m, __shfl_xor_sync(0xffffffffu, m, o));

    __shared__ float red_max[8];
    __shared__ float red_sum[8];
    if ((tid & 31) == 0) red_max[tid >> 5] = m;
    __syncthreads();
    m = fmaxf(fmaxf(fmaxf(red_max[0], red_max[1]), fmaxf(red_max[2], red_max[3])),
              fmaxf(fmaxf(red_max[4], red_max[5]), fmaxf(red_max[6], red_max[7])));

    float e[8];
    e[0] = __expf(v0.x - m); e[1] = __expf(v0.y - m);
    e[2] = __expf(v0.z - m); e[3] = __expf(v0.w - m);
    e[4] = __expf(v1.x - m); e[5] = __expf(v1.y - m);
    e[6] = __expf(v1.z - m); e[7] = __expf(v1.w - m);

    float s = ((e[0] + e[1]) + (e[2] + e[3])) + ((e[4] + e[5]) + (e[6] + e[7]));
#pragma unroll
    for (int o = 16; o > 0; o >>= 1)
        s += __shfl_xor_sync(0xffffffffu, s, o);
    if ((tid & 31) == 0) red_sum[tid >> 5] = s;
    __syncthreads();
    const float l = ((red_sum[0] + red_sum[1]) + (red_sum[2] + red_sum[3])) +
                    ((red_sum[4] + red_sum[5]) + (red_sum[6] + red_sum[7]));
    const float inv = 1.0f / l;

    float4 p0 = make_float4(e[0] * inv, e[1] * inv, e[2] * inv, e[3] * inv);
    float4 p1 = make_float4(e[4] * inv, e[5] * inv, e[6] * inv, e[7] * inv);
    uint2 h0, l0, h1, l1;
    split4(p0, h0, l0); split4(p1, h1, l1);
    *(uint2*)(P + 4 * tid)             = h0;
    *(uint2*)(P + 1024 + 4 * tid)      = h1;
    *(uint2*)(P + TK + 4 * tid)        = l0;
    *(uint2*)(P + TK + 1024 + 4 * tid) = l1;
}

// ---------------------------------------------------------------------------
// kernel_launch: Q = d_in[0] (32,512,512) fp32, E = d_in[1] (32,2048,512) fp32
// ---------------------------------------------------------------------------
extern "C" void kernel_launch(void* const* d_in, const int* in_sizes, int n_in,
                              void* d_out, int out_size) {
    (void)in_sizes; (void)n_in; (void)out_size;
    const float* Q = (const float*)d_in[0];
    const float* E = (const float*)d_in[1];
    float* O = (float*)d_out;

    cudaFuncSetAttribute(gemm_mma<0>, cudaFuncAttributeMaxDynamicSharedMemorySize, GSM);
    cudaFuncSetAttribute(gemm_mma<1>, cudaFuncAttributeMaxDynamicSharedMemorySize, GSM);

    splitQ_kernel<<<(BATCH * TQ * 64 + 255) / 256, 256>>>(Q);
    splitE_transpose_kernel<<<dim3(TK / 64, DIM / 64, BATCH), 256>>>(E);

    gemm_mma<0><<<dim3(TK / 256, TQ / 128, BATCH), 512, GSM>>>(nullptr);
    softmax_split_kernel<<<BATCH * TQ, 256>>>();
    gemm_mma<1><<<dim3(DIM / 256, TQ / 128, BATCH), 512, GSM>>>(O);
}

// round 15
// speedup vs baseline: 1.0345x; 1.0345x over previous
#include <cuda_runtime.h>
#include <cuda_bf16.h>
#include <cstdint>
#include <cstddef>

#define BATCH 32
#define TQ    512
#define TK    2048
#define DIM   512

// ---------------------------------------------------------------------------
// Static device scratch.
// ---------------------------------------------------------------------------
__device__ float    g_S [(size_t)BATCH * TQ * TK];
__device__ uint16_t g_Q2[(size_t)BATCH * TQ  * (2 * DIM)];
__device__ uint16_t g_E2[(size_t)BATCH * TK  * (2 * DIM)];
__device__ uint16_t g_Et[(size_t)BATCH * DIM * (2 * TK)];
__device__ uint16_t g_P2[(size_t)BATCH * TQ  * (2 * TK)];

// ---------------------------------------------------------------------------
// Base-PTX helpers (sm_80+ only — must compile for compute_103)
// ---------------------------------------------------------------------------
__device__ __forceinline__ uint32_t smem_u32(const void* p) {
    uint32_t a;
    asm("{ .reg .u64 t; cvta.to.shared.u64 t, %1; cvt.u32.u64 %0, t; }"
        : "=r"(a) : "l"(p));
    return a;
}

__device__ __forceinline__ void cp16(uint32_t saddr, const void* gaddr) {
    asm volatile("cp.async.cg.shared.global [%0], [%1], 16;\n"
                 :: "r"(saddr), "l"(gaddr));
}
__device__ __forceinline__ void cp_commit() {
    asm volatile("cp.async.commit_group;\n" ::: "memory");
}
template <int N>
__device__ __forceinline__ void cp_wait() {
    asm volatile("cp.async.wait_group %0;\n" :: "n"(N) : "memory");
}

__device__ __forceinline__ void ldsm4(uint32_t& r0, uint32_t& r1,
                                      uint32_t& r2, uint32_t& r3, uint32_t a) {
    asm volatile("ldmatrix.sync.aligned.m8n8.x4.shared.b16 {%0,%1,%2,%3}, [%4];\n"
                 : "=r"(r0), "=r"(r1), "=r"(r2), "=r"(r3) : "r"(a));
}

__device__ __forceinline__ void mma16816(float* c, const uint32_t* a,
                                         const uint32_t* b) {
    asm volatile(
        "mma.sync.aligned.m16n8k16.row.col.f32.bf16.bf16.f32 "
        "{%0,%1,%2,%3}, {%4,%5,%6,%7}, {%8,%9}, {%0,%1,%2,%3};\n"
        : "+f"(c[0]), "+f"(c[1]), "+f"(c[2]), "+f"(c[3])
        : "r"(a[0]), "r"(a[1]), "r"(a[2]), "r"(a[3]), "r"(b[0]), "r"(b[1]));
}

// ---------------------------------------------------------------------------
// fp32 -> (bf16 hi, bf16 lo) split helpers
// ---------------------------------------------------------------------------
__device__ __forceinline__ void split4(float4 v, uint2& hi, uint2& lo) {
    __nv_bfloat16 h0 = __float2bfloat16_rn(v.x);
    __nv_bfloat16 h1 = __float2bfloat16_rn(v.y);
    __nv_bfloat16 h2 = __float2bfloat16_rn(v.z);
    __nv_bfloat16 h3 = __float2bfloat16_rn(v.w);
    __nv_bfloat16 l0 = __float2bfloat16_rn(v.x - __bfloat162float(h0));
    __nv_bfloat16 l1 = __float2bfloat16_rn(v.y - __bfloat162float(h1));
    __nv_bfloat16 l2 = __float2bfloat16_rn(v.z - __bfloat162float(h2));
    __nv_bfloat16 l3 = __float2bfloat16_rn(v.w - __bfloat162float(h3));
    hi.x = (uint32_t)__bfloat16_as_ushort(h0) | ((uint32_t)__bfloat16_as_ushort(h1) << 16);
    hi.y = (uint32_t)__bfloat16_as_ushort(h2) | ((uint32_t)__bfloat16_as_ushort(h3) << 16);
    lo.x = (uint32_t)__bfloat16_as_ushort(l0) | ((uint32_t)__bfloat16_as_ushort(l1) << 16);
    lo.y = (uint32_t)__bfloat16_as_ushort(l2) | ((uint32_t)__bfloat16_as_ushort(l3) << 16);
}

// ---------------------------------------------------------------------------
// splitQ: Q[r, 0..511] fp32 -> g_Q2[r, hi(512)|lo(512)] bf16
// ---------------------------------------------------------------------------
__global__ __launch_bounds__(256) void splitQ_kernel(const float* __restrict__ Q) {
    size_t t = (size_t)blockIdx.x * 256 + threadIdx.x;
    if (t >= (size_t)BATCH * TQ * 64) return;
    size_t row = t >> 6;
    int g = (int)(t & 63);
    const float4* p = (const float4*)(Q + row * DIM) + g * 2;
    float4 a = p[0], b = p[1];
    uint2 h0, l0, h1, l1;
    split4(a, h0, l0); split4(b, h1, l1);
    uint16_t* orow = g_Q2 + row * (2 * DIM);
    *(uint4*)(orow + g * 8)       = make_uint4(h0.x, h0.y, h1.x, h1.y);
    *(uint4*)(orow + DIM + g * 8) = make_uint4(l0.x, l0.y, l1.x, l1.y);
}

// ---------------------------------------------------------------------------
// Fused splitE + transposeE: read each 64x64 E tile ONCE, emit both
//   g_E2[b, k, hi(d)|lo(d)]  and  g_Et[b, d, hi(k)|lo(k)]
// ---------------------------------------------------------------------------
__global__ __launch_bounds__(256)
void splitE_transpose_kernel(const float* __restrict__ Eg) {
    __shared__ float t[64][65];
    const int b = blockIdx.z, k0 = blockIdx.x * 64, d0 = blockIdx.y * 64;
    const float* E = Eg + (size_t)b * TK * DIM;
    const int tid = threadIdx.x;
#pragma unroll
    for (int i = 0; i < 4; ++i) {
        int idx = tid + i * 256;
        int r = idx >> 4, c4 = idx & 15;
        float4 v = *(const float4*)(E + (size_t)(k0 + r) * DIM + d0 + c4 * 4);
        t[r][c4 * 4 + 0] = v.x; t[r][c4 * 4 + 1] = v.y;
        t[r][c4 * 4 + 2] = v.z; t[r][c4 * 4 + 3] = v.w;
    }
    __syncthreads();

    uint16_t* E2 = g_E2 + (size_t)b * TK * (2 * DIM);
#pragma unroll
    for (int i = 0; i < 2; ++i) {
        int task = tid + i * 256;
        int r = task >> 3, g = task & 7;
        float4 a = make_float4(t[r][g*8+0], t[r][g*8+1], t[r][g*8+2], t[r][g*8+3]);
        float4 c = make_float4(t[r][g*8+4], t[r][g*8+5], t[r][g*8+6], t[r][g*8+7]);
        uint2 h0, l0, h1, l1;
        split4(a, h0, l0); split4(c, h1, l1);
        uint16_t* orow = E2 + (size_t)(k0 + r) * (2 * DIM);
        *(uint4*)(orow + d0 + g * 8)       = make_uint4(h0.x, h0.y, h1.x, h1.y);
        *(uint4*)(orow + DIM + d0 + g * 8) = make_uint4(l0.x, l0.y, l1.x, l1.y);
    }

    uint16_t* Et = g_Et + (size_t)b * DIM * (2 * TK);
#pragma unroll
    for (int i = 0; i < 2; ++i) {
        int task = tid + i * 256;
        int dr = task >> 3, g = task & 7;
        float4 a = make_float4(t[g*8+0][dr], t[g*8+1][dr], t[g*8+2][dr], t[g*8+3][dr]);
        float4 c = make_float4(t[g*8+4][dr], t[g*8+5][dr], t[g*8+6][dr], t[g*8+7][dr]);
        uint2 h0, l0, h1, l1;
        split4(a, h0, l0); split4(c, h1, l1);
        uint16_t* orow = Et + (size_t)(d0 + dr) * (2 * TK);
        *(uint4*)(orow + k0 + g * 8)      = make_uint4(h0.x, h0.y, h1.x, h1.y);
        *(uint4*)(orow + TK + k0 + g * 8) = make_uint4(l0.x, l0.y, l1.x, l1.y);
    }
}

// ---------------------------------------------------------------------------
// NT GEMM, fused 3-phase split per 32-k chunk (hh, hl, lh).
// NEW STRUCTURE: 256 threads/CTA (8 warps), CTA tile 128(M) x 128(N),
// warp tile 64x32, 2 CTAs/SM (launch_bounds(256,2)), 3-stage cp.async
// pipeline with ONE __syncthreads per chunk. Two co-resident CTAs keep the
// HMMA pipe fed while the other CTA is in barrier/ldmatrix phases.
// Smem/stage: A 16 KB + B 16 KB; 3 stages = 96 KB dynamic.
// MODE 0: S = Q2 * E2^T (Kp=512)    MODE 1: O = P2 * Et^T (Kp=2048)
// ---------------------------------------------------------------------------
#define STG  32768   // bytes per pipeline stage (A 16K + B 16K)
#define GSM  98304   // 3 stages

template <int MODE>
__global__ __launch_bounds__(256, 2)
void gemm_mma(float* __restrict__ Oout) {
    constexpr int Kp  = MODE ? 2048 : 512;
    constexpr int NCH = Kp / 32;          // chunks (16 / 64)
    constexpr int lda = MODE ? 2 * TK : 2 * DIM;
    constexpr int ldb = MODE ? 2 * TK : 2 * DIM;
    constexpr int ldc = MODE ? DIM : TK;

    extern __shared__ char smem[];
    const uint32_t sb = smem_u32(smem);

    const int tid  = threadIdx.x;
    const int wid  = tid >> 5;
    const int lane = tid & 31;
    const int warp_m = wid & 1;           // 0..1  (64 rows each)
    const int warp_n = wid >> 1;          // 0..3  (32 cols each)

    const int b  = blockIdx.z;
    const int n0 = blockIdx.x * 128;
    const int q0 = blockIdx.y * 128;

    const uint16_t* A = (MODE ? g_P2 : g_Q2) + (size_t)b * TQ * lda + (size_t)q0 * lda;
    const uint16_t* B = (MODE ? g_Et : g_E2) +
                        (size_t)b * (size_t)(MODE ? DIM : TK) * ldb + (size_t)n0 * ldb;
    float* C = (MODE ? Oout + (size_t)b * TQ * DIM : g_S + (size_t)b * TQ * TK);

    // cp.async: A = 1024 16B-segs (4/thread), B = 1024 (4/thread).
    // segs 0-3 <- hi half (koff), segs 4-7 <- lo half (Kp + koff).
    // dst swizzle: seg' = seg ^ (row & 7).
    auto issue_chunk = [&](int stage, int c) {
        const int koff = c * 32;
        const uint32_t abase = sb + stage * STG;
        const uint32_t bbase = abase + 16384;
#pragma unroll
        for (int j = 0; j < 4; ++j) {
            int idx = tid + j * 256;
            int row = idx >> 3, seg = idx & 7;
            const uint16_t* src = A + (size_t)row * lda +
                (seg < 4 ? koff + seg * 8 : Kp + koff + (seg - 4) * 8);
            cp16(abase + row * 128 + ((seg ^ (row & 7)) << 4), src);
        }
#pragma unroll
        for (int j = 0; j < 4; ++j) {
            int idx = tid + j * 256;
            int row = idx >> 3, seg = idx & 7;
            const uint16_t* src = B + (size_t)row * ldb +
                (seg < 4 ? koff + seg * 8 : Kp + koff + (seg - 4) * 8);
            cp16(bbase + row * 128 + ((seg ^ (row & 7)) << 4), src);
        }
        cp_commit();
    };

    float acc[4][4][4];
#pragma unroll
    for (int i = 0; i < 4; ++i)
#pragma unroll
        for (int j = 0; j < 4; ++j)
#pragma unroll
            for (int k = 0; k < 4; ++k) acc[i][j][k] = 0.0f;

    // ldmatrix lane geometry (validated layout)
    const int aRowBase = warp_m * 64 + ((lane >> 3) & 1) * 8 + (lane & 7);
    const int aSegSel  = lane >> 4;                 // 0/1
    const int bRowBase = warp_n * 32 + ((lane >> 4) & 1) * 8 + (lane & 7);
    const int bSegSel  = (lane >> 3) & 1;           // 0/1

    int aRow[4], bRow[2];
#pragma unroll
    for (int mt = 0; mt < 4; ++mt) aRow[mt] = aRowBase + mt * 16;
#pragma unroll
    for (int np = 0; np < 2; ++np) bRow[np] = bRowBase + np * 16;

    // 3-stage pipeline prologue
    issue_chunk(0, 0);
    if (NCH > 1) issue_chunk(1, 1);

    int stage = 0;
    for (int c = 0; c < NCH; ++c) {
        if (c + 2 < NCH) cp_wait<1>();
        else             cp_wait<0>();
        __syncthreads();                    // all warps done with stage (c-1)%3
        if (c + 2 < NCH) issue_chunk((stage + 2) % 3, c + 2);

        const uint32_t abase = sb + stage * STG;
        const uint32_t bbase = abase + 16384;
#pragma unroll
        for (int ks = 0; ks < 2; ++ks) {
            // --- hi fragments ---
            uint32_t afh[4][4];
#pragma unroll
            for (int mt = 0; mt < 4; ++mt) {
                const int r = aRow[mt];
                const uint32_t ad =
                    abase + r * 128 + (((2 * ks + aSegSel) ^ (r & 7)) << 4);
                ldsm4(afh[mt][0], afh[mt][1], afh[mt][2], afh[mt][3], ad);
            }
            uint32_t bfh[4][2];
#pragma unroll
            for (int np = 0; np < 2; ++np) {
                const int r = bRow[np];
                const uint32_t bd =
                    bbase + r * 128 + (((2 * ks + bSegSel) ^ (r & 7)) << 4);
                ldsm4(bfh[np * 2][0], bfh[np * 2][1],
                      bfh[np * 2 + 1][0], bfh[np * 2 + 1][1], bd);
            }
            // hh
#pragma unroll
            for (int mt = 0; mt < 4; ++mt)
#pragma unroll
                for (int nt = 0; nt < 4; ++nt)
                    mma16816(acc[mt][nt], afh[mt], bfh[nt]);

            // --- B lo, then hl (Ahi still live) ---
            uint32_t bfl[4][2];
#pragma unroll
            for (int np = 0; np < 2; ++np) {
                const int r = bRow[np];
                const uint32_t bd =
                    bbase + r * 128 + (((4 + 2 * ks + bSegSel) ^ (r & 7)) << 4);
                ldsm4(bfl[np * 2][0], bfl[np * 2][1],
                      bfl[np * 2 + 1][0], bfl[np * 2 + 1][1], bd);
            }
#pragma unroll
            for (int mt = 0; mt < 4; ++mt)
#pragma unroll
                for (int nt = 0; nt < 4; ++nt)
                    mma16816(acc[mt][nt], afh[mt], bfl[nt]);

            // --- A lo, then lh (Bhi still live; Ahi dead) ---
            uint32_t afl[4][4];
#pragma unroll
            for (int mt = 0; mt < 4; ++mt) {
                const int r = aRow[mt];
                const uint32_t ad =
                    abase + r * 128 + (((4 + 2 * ks + aSegSel) ^ (r & 7)) << 4);
                ldsm4(afl[mt][0], afl[mt][1], afl[mt][2], afl[mt][3], ad);
            }
#pragma unroll
            for (int mt = 0; mt < 4; ++mt)
#pragma unroll
                for (int nt = 0; nt < 4; ++nt)
                    mma16816(acc[mt][nt], afl[mt], bfh[nt]);
        }
        stage = (stage + 1) % 3;
    }

    // epilogue
    const int fr = lane >> 2;
    const int fc = (lane & 3) * 2;
#pragma unroll
    for (int mt = 0; mt < 4; ++mt) {
        const int row = q0 + warp_m * 64 + mt * 16 + fr;
#pragma unroll
        for (int nt = 0; nt < 4; ++nt) {
            const int col = n0 + warp_n * 32 + nt * 8 + fc;
            *(float2*)&C[(size_t)row * ldc + col] =
                make_float2(acc[mt][nt][0], acc[mt][nt][1]);
            *(float2*)&C[(size_t)(row + 8) * ldc + col] =
                make_float2(acc[mt][nt][2], acc[mt][nt][3]);
        }
    }
}

// ---------------------------------------------------------------------------
// Softmax over S rows; emits P split: g_P2[row] = [Phi(2048) | Plo(2048)]
// ---------------------------------------------------------------------------
__global__ __launch_bounds__(256)
void softmax_split_kernel() {
    const int row = blockIdx.x;
    const float4* S4 = (const float4*)g_S + (size_t)row * (TK / 4);
    uint16_t* P = g_P2 + (size_t)row * (2 * TK);
    const int tid = threadIdx.x;

    float4 v0 = S4[tid];
    float4 v1 = S4[tid + 256];

    float m = fmaxf(fmaxf(fmaxf(v0.x, v0.y), fmaxf(v0.z, v0.w)),
                    fmaxf(fmaxf(v1.x, v1.y), fmaxf(v1.z, v1.w)));
#pragma unroll
    for (int o = 16; o > 0; o >>= 1)
        m = fmaxf(m, __shfl_xor_sync(0xffffffffu, m, o));

    __shared__ float red_max[8];
    __shared__ float red_sum[8];
    if ((tid & 31) == 0) red_max[tid >> 5] = m;
    __syncthreads();
    m = fmaxf(fmaxf(fmaxf(red_max[0], red_max[1]), fmaxf(red_max[2], red_max[3])),
              fmaxf(fmaxf(red_max[4], red_max[5]), fmaxf(red_max[6], red_max[7])));

    float e[8];
    e[0] = __expf(v0.x - m); e[1] = __expf(v0.y - m);
    e[2] = __expf(v0.z - m); e[3] = __expf(v0.w - m);
    e[4] = __expf(v1.x - m); e[5] = __expf(v1.y - m);
    e[6] = __expf(v1.z - m); e[7] = __expf(v1.w - m);

    float s = ((e[0] + e[1]) + (e[2] + e[3])) + ((e[4] + e[5]) + (e[6] + e[7]));
#pragma unroll
    for (int o = 16; o > 0; o >>= 1)
        s += __shfl_xor_sync(0xffffffffu, s, o);
    if ((tid & 31) == 0) red_sum[tid >> 5] = s;
    __syncthreads();
    const float l = ((red_sum[0] + red_sum[1]) + (red_sum[2] + red_sum[3])) +
                    ((red_sum[4] + red_sum[5]) + (red_sum[6] + red_sum[7]));
    const float inv = 1.0f / l;

    float4 p0 = make_float4(e[0] * inv, e[1] * inv, e[2] * inv, e[3] * inv);
    float4 p1 = make_float4(e[4] * inv, e[5] * inv, e[6] * inv, e[7] * inv);
    uint2 h0, l0, h1, l1;
    split4(p0, h0, l0); split4(p1, h1, l1);
    *(uint2*)(P + 4 * tid)             = h0;
    *(uint2*)(P + 1024 + 4 * tid)      = h1;
    *(uint2*)(P + TK + 4 * tid)        = l0;
    *(uint2*)(P + TK + 1024 + 4 * tid) = l1;
}

// ---------------------------------------------------------------------------
// kernel_launch: Q = d_in[0] (32,512,512) fp32, E = d_in[1] (32,2048,512) fp32
// ---------------------------------------------------------------------------
extern "C" void kernel_launch(void* const* d_in, const int* in_sizes, int n_in,
                              void* d_out, int out_size) {
    (void)in_sizes; (void)n_in; (void)out_size;
    const float* Q = (const float*)d_in[0];
    const float* E = (const float*)d_in[1];
    float* O = (float*)d_out;

    cudaFuncSetAttribute(gemm_mma<0>, cudaFuncAttributeMaxDynamicSharedMemorySize, GSM);
    cudaFuncSetAttribute(gemm_mma<1>, cudaFuncAttributeMaxDynamicSharedMemorySize, GSM);

    splitQ_kernel<<<(BATCH * TQ * 64 + 255) / 256, 256>>>(Q);
    splitE_transpose_kernel<<<dim3(TK / 64, DIM / 64, BATCH), 256>>>(E);

    gemm_mma<0><<<dim3(TK / 128, TQ / 128, BATCH), 256, GSM>>>(nullptr); // (16,4,32)
    softmax_split_kernel<<<BATCH * TQ, 256>>>();
    gemm_mma<1><<<dim3(DIM / 128, TQ / 128, BATCH), 256, GSM>>>(O);      // (4,4,32)
}